// round 1
// baseline (speedup 1.0000x reference)
#include <cuda_runtime.h>
#include <cuda_bf16.h>

#define NA 100000
#define NB 50000
#define DIM 128
#define EE 1000000

// ---- static device scratch (no allocation allowed in kernel_launch) ----
__device__ float g_h_ab[(size_t)NA * DIM];   // x_a @ W_ab  -> scattered to out_b
__device__ float g_h_ba[(size_t)NB * DIM];   // x_b @ W_ba  -> scattered to out_a
__device__ float g_h_aa[(size_t)NA * DIM];   // x_a @ W_aa  -> scattered to out_a

__device__ int g_deg_s_ab[NA];
__device__ int g_deg_t_ab[NB];
__device__ int g_deg_s_ba[NB];
__device__ int g_deg_t_ba[NA];
__device__ int g_deg_s_aa[NA];
__device__ int g_deg_t_aa[NA];

// ---------------------------------------------------------------------
// Zero output accumulator + degree arrays
// ---------------------------------------------------------------------
__global__ void zero_kernel(float* __restrict__ out, int n_out_f4) {
    int i = blockIdx.x * blockDim.x + threadIdx.x;
    int stride = gridDim.x * blockDim.x;
    float4 z = make_float4(0.f, 0.f, 0.f, 0.f);
    for (int j = i; j < n_out_f4; j += stride)
        reinterpret_cast<float4*>(out)[j] = z;
    for (int j = i; j < NA; j += stride) {
        g_deg_s_ab[j] = 0;
        g_deg_t_ba[j] = 0;
        g_deg_s_aa[j] = 0;
        g_deg_t_aa[j] = 0;
    }
    for (int j = i; j < NB; j += stride) {
        g_deg_t_ab[j] = 0;
        g_deg_s_ba[j] = 0;
    }
}

// ---------------------------------------------------------------------
// Degree histograms for all 3 edge types
// ---------------------------------------------------------------------
__global__ void degree_kernel(const int* __restrict__ src_ab, const int* __restrict__ dst_ab,
                              const int* __restrict__ src_ba, const int* __restrict__ dst_ba,
                              const int* __restrict__ src_aa, const int* __restrict__ dst_aa) {
    int i = blockIdx.x * blockDim.x + threadIdx.x;
    if (i >= EE) return;
    atomicAdd(&g_deg_s_ab[src_ab[i]], 1);
    atomicAdd(&g_deg_t_ab[dst_ab[i]], 1);
    atomicAdd(&g_deg_s_ba[src_ba[i]], 1);
    atomicAdd(&g_deg_t_ba[dst_ba[i]], 1);
    atomicAdd(&g_deg_s_aa[src_aa[i]], 1);
    atomicAdd(&g_deg_t_aa[dst_aa[i]], 1);
}

// ---------------------------------------------------------------------
// SGEMM: H[nrows,128] = X[nrows,128] @ W[128,128], fp32
// BM=64, BN=128, BK=32, 256 threads, per-thread 8x4 micro-tile.
// ---------------------------------------------------------------------
__global__ __launch_bounds__(256) void gemm128_kernel(const float* __restrict__ X,
                                                      const float* __restrict__ W,
                                                      float* __restrict__ H, int nrows) {
    __shared__ float As[32][65];    // [k][m], padded to dodge STS bank conflicts
    __shared__ float Bs[32][128];   // [k][n]

    const int t = threadIdx.x;
    const int tn = t & 31;   // col group (4 cols)
    const int tm = t >> 5;   // row group (8 rows); constant per warp -> broadcast LDS
    const int row0 = blockIdx.x * 64;

    float acc[8][4];
#pragma unroll
    for (int i = 0; i < 8; i++)
#pragma unroll
        for (int j = 0; j < 4; j++) acc[i][j] = 0.f;

    for (int k0 = 0; k0 < 128; k0 += 32) {
        // A tile: 64 rows x 32 k, float4 along k (512 float4 / 256 thr = 2 each)
#pragma unroll
        for (int l = 0; l < 2; l++) {
            int i = t + l * 256;         // 0..511
            int r = i >> 3;              // 0..63
            int kq = (i & 7) * 4;        // 0,4,...,28
            float4 v = make_float4(0.f, 0.f, 0.f, 0.f);
            if (row0 + r < nrows)
                v = *reinterpret_cast<const float4*>(&X[(size_t)(row0 + r) * DIM + k0 + kq]);
            As[kq + 0][r] = v.x;
            As[kq + 1][r] = v.y;
            As[kq + 2][r] = v.z;
            As[kq + 3][r] = v.w;
        }
        // B tile: 32 k x 128 n, contiguous (1024 float4 / 256 thr = 4 each)
#pragma unroll
        for (int l = 0; l < 4; l++) {
            int i = t + l * 256;
            reinterpret_cast<float4*>(&Bs[0][0])[i] =
                reinterpret_cast<const float4*>(&W[(size_t)k0 * DIM])[i];
        }
        __syncthreads();

#pragma unroll
        for (int k = 0; k < 32; k++) {
            float a[8], b[4];
#pragma unroll
            for (int i = 0; i < 8; i++) a[i] = As[k][tm * 8 + i];   // broadcast within warp
            float4 bv = *reinterpret_cast<const float4*>(&Bs[k][tn * 4]);
            b[0] = bv.x; b[1] = bv.y; b[2] = bv.z; b[3] = bv.w;
#pragma unroll
            for (int i = 0; i < 8; i++)
#pragma unroll
                for (int j = 0; j < 4; j++) acc[i][j] += a[i] * b[j];
        }
        __syncthreads();
    }

#pragma unroll
    for (int i = 0; i < 8; i++) {
        int r = row0 + tm * 8 + i;
        if (r < nrows) {
            float4 v = make_float4(acc[i][0], acc[i][1], acc[i][2], acc[i][3]);
            *reinterpret_cast<float4*>(&H[(size_t)r * DIM + tn * 4]) = v;
        }
    }
}

// ---------------------------------------------------------------------
// Fused edge scatter: one warp per edge (3E edges total).
// lane handles 4 consecutive floats of the 128-wide row.
// ---------------------------------------------------------------------
__global__ __launch_bounds__(256) void scatter_kernel(
    const int* __restrict__ src_ab, const int* __restrict__ dst_ab,
    const int* __restrict__ src_ba, const int* __restrict__ dst_ba,
    const int* __restrict__ src_aa, const int* __restrict__ dst_aa,
    float* __restrict__ out_a, float* __restrict__ out_b) {

    long long gw = (long long)blockIdx.x * (blockDim.x >> 5) + (threadIdx.x >> 5);
    int lane = threadIdx.x & 31;
    if (gw >= 3LL * EE) return;

    const float* h;
    float* out;
    const int* sp;
    const int* dp;
    const int* degs;
    const int* degt;
    long long e;
    if (gw < EE) {
        e = gw;            sp = src_ab; dp = dst_ab; h = g_h_ab; out = out_b;
        degs = g_deg_s_ab; degt = g_deg_t_ab;
    } else if (gw < 2LL * EE) {
        e = gw - EE;       sp = src_ba; dp = dst_ba; h = g_h_ba; out = out_a;
        degs = g_deg_s_ba; degt = g_deg_t_ba;
    } else {
        e = gw - 2LL * EE; sp = src_aa; dp = dst_aa; h = g_h_aa; out = out_a;
        degs = g_deg_s_aa; degt = g_deg_t_aa;
    }

    int s = sp[e];
    int d = dp[e];
    float inv = rsqrtf((float)degs[s] * (float)degt[d]);

    float4 v = *reinterpret_cast<const float4*>(&h[(size_t)s * DIM + lane * 4]);
    float* o = &out[(size_t)d * DIM + lane * 4];
    atomicAdd(o + 0, v.x * inv);
    atomicAdd(o + 1, v.y * inv);
    atomicAdd(o + 2, v.z * inv);
    atomicAdd(o + 3, v.w * inv);
}

// ---------------------------------------------------------------------
// Finalize: out_a *= 0.5, ReLU everywhere (in place on d_out)
// ---------------------------------------------------------------------
__global__ void finalize_kernel(float* __restrict__ out) {
    const int nA4 = NA * DIM / 4;
    const int nTot4 = (NA + NB) * DIM / 4;
    int i = blockIdx.x * blockDim.x + threadIdx.x;
    if (i >= nTot4) return;
    float4 v = reinterpret_cast<float4*>(out)[i];
    if (i < nA4) {
        v.x *= 0.5f; v.y *= 0.5f; v.z *= 0.5f; v.w *= 0.5f;
    }
    v.x = fmaxf(v.x, 0.f);
    v.y = fmaxf(v.y, 0.f);
    v.z = fmaxf(v.z, 0.f);
    v.w = fmaxf(v.w, 0.f);
    reinterpret_cast<float4*>(out)[i] = v;
}

// ---------------------------------------------------------------------
extern "C" void kernel_launch(void* const* d_in, const int* in_sizes, int n_in,
                              void* d_out, int out_size) {
    const float* x_a  = (const float*)d_in[0];
    const float* x_b  = (const float*)d_in[1];
    const float* W_ab = (const float*)d_in[2];
    const float* W_ba = (const float*)d_in[3];
    const float* W_aa = (const float*)d_in[4];
    const int* src_ab = (const int*)d_in[5];
    const int* dst_ab = (const int*)d_in[6];
    const int* src_ba = (const int*)d_in[7];
    const int* dst_ba = (const int*)d_in[8];
    const int* src_aa = (const int*)d_in[9];
    const int* dst_aa = (const int*)d_in[10];

    float* out   = (float*)d_out;
    float* out_a = out;                       // [NA,128]
    float* out_b = out + (size_t)NA * DIM;    // [NB,128]

    // Resolve scratch symbol addresses (host API, not an allocation).
    float *h_ab, *h_ba, *h_aa;
    cudaGetSymbolAddress((void**)&h_ab, g_h_ab);
    cudaGetSymbolAddress((void**)&h_ba, g_h_ba);
    cudaGetSymbolAddress((void**)&h_aa, g_h_aa);

    const int nTotF4 = (NA + NB) * DIM / 4;

    zero_kernel<<<1024, 256>>>(out, nTotF4);

    degree_kernel<<<(EE + 255) / 256, 256>>>(src_ab, dst_ab, src_ba, dst_ba, src_aa, dst_aa);

    gemm128_kernel<<<(NA + 63) / 64, 256>>>(x_a, W_ab, h_ab, NA);
    gemm128_kernel<<<(NB + 63) / 64, 256>>>(x_b, W_ba, h_ba, NB);
    gemm128_kernel<<<(NA + 63) / 64, 256>>>(x_a, W_aa, h_aa, NA);

    // 3E edges, one warp per edge, 8 warps per block
    long long nwarps = 3LL * EE;
    int blocks = (int)((nwarps + 7) / 8);
    scatter_kernel<<<blocks, 256>>>(src_ab, dst_ab, src_ba, dst_ba, src_aa, dst_aa,
                                    out_a, out_b);

    finalize_kernel<<<(nTotF4 + 255) / 256, 256>>>(out);
}

// round 2
// speedup vs baseline: 1.6755x; 1.6755x over previous
#include <cuda_runtime.h>
#include <cuda_bf16.h>

#define NA 100000
#define NB 50000
#define DIM 128
#define EE 1000000

// ---- static device scratch (no allocation allowed in kernel_launch) ----
__device__ float g_h_ab[(size_t)NA * DIM];   // (x_a @ W_ab) * rsqrt(deg_s_ab)  -> out_b
__device__ float g_h_ba[(size_t)NB * DIM];   // (x_b @ W_ba) * rsqrt(deg_s_ba)  -> out_a
__device__ float g_h_aa[(size_t)NA * DIM];   // (x_a @ W_aa) * rsqrt(deg_s_aa)  -> out_a

__device__ int g_deg_s_ab[NA];
__device__ int g_deg_t_ab[NB];
__device__ int g_deg_s_ba[NB];
__device__ int g_deg_t_ba[NA];
__device__ int g_deg_s_aa[NA];
__device__ int g_deg_t_aa[NA];

// 16-byte vector reduction (sm_90+): one RED instead of 4 scalar atomics
__device__ __forceinline__ void red_add_v4(float* addr, float x, float y, float z, float w) {
    asm volatile("red.global.add.v4.f32 [%0], {%1, %2, %3, %4};"
                 :: "l"(addr), "f"(x), "f"(y), "f"(z), "f"(w) : "memory");
}

// ---------------------------------------------------------------------
// Zero output accumulator + degree arrays
// ---------------------------------------------------------------------
__global__ void zero_kernel(float* __restrict__ out, int n_out_f4) {
    int i = blockIdx.x * blockDim.x + threadIdx.x;
    int stride = gridDim.x * blockDim.x;
    float4 z = make_float4(0.f, 0.f, 0.f, 0.f);
    for (int j = i; j < n_out_f4; j += stride)
        reinterpret_cast<float4*>(out)[j] = z;
    for (int j = i; j < NA; j += stride) {
        g_deg_s_ab[j] = 0;
        g_deg_t_ba[j] = 0;
        g_deg_s_aa[j] = 0;
        g_deg_t_aa[j] = 0;
    }
    for (int j = i; j < NB; j += stride) {
        g_deg_t_ab[j] = 0;
        g_deg_s_ba[j] = 0;
    }
}

// ---------------------------------------------------------------------
// Degree histograms for all 3 edge types
// ---------------------------------------------------------------------
__global__ void degree_kernel(const int* __restrict__ src_ab, const int* __restrict__ dst_ab,
                              const int* __restrict__ src_ba, const int* __restrict__ dst_ba,
                              const int* __restrict__ src_aa, const int* __restrict__ dst_aa) {
    int i = blockIdx.x * blockDim.x + threadIdx.x;
    if (i >= EE) return;
    atomicAdd(&g_deg_s_ab[src_ab[i]], 1);
    atomicAdd(&g_deg_t_ab[dst_ab[i]], 1);
    atomicAdd(&g_deg_s_ba[src_ba[i]], 1);
    atomicAdd(&g_deg_t_ba[dst_ba[i]], 1);
    atomicAdd(&g_deg_s_aa[src_aa[i]], 1);
    atomicAdd(&g_deg_t_aa[dst_aa[i]], 1);
}

// ---------------------------------------------------------------------
// SGEMM: H[nrows,128] = (X[nrows,128] @ W[128,128]) * rsqrt(deg_s[row]), fp32
// BM=64, BN=128, BK=32, 256 threads, per-thread 8x4 micro-tile.
// ---------------------------------------------------------------------
__global__ __launch_bounds__(256) void gemm128_kernel(const float* __restrict__ X,
                                                      const float* __restrict__ W,
                                                      float* __restrict__ H,
                                                      const int* __restrict__ degs,
                                                      int nrows) {
    __shared__ float As[32][65];    // [k][m], padded
    __shared__ float Bs[32][128];   // [k][n]

    const int t = threadIdx.x;
    const int tn = t & 31;   // col group (4 cols)
    const int tm = t >> 5;   // row group (8 rows); constant per warp -> broadcast LDS
    const int row0 = blockIdx.x * 64;

    float acc[8][4];
#pragma unroll
    for (int i = 0; i < 8; i++)
#pragma unroll
        for (int j = 0; j < 4; j++) acc[i][j] = 0.f;

    for (int k0 = 0; k0 < 128; k0 += 32) {
#pragma unroll
        for (int l = 0; l < 2; l++) {
            int i = t + l * 256;         // 0..511
            int r = i >> 3;              // 0..63
            int kq = (i & 7) * 4;        // 0,4,...,28
            float4 v = make_float4(0.f, 0.f, 0.f, 0.f);
            if (row0 + r < nrows)
                v = *reinterpret_cast<const float4*>(&X[(size_t)(row0 + r) * DIM + k0 + kq]);
            As[kq + 0][r] = v.x;
            As[kq + 1][r] = v.y;
            As[kq + 2][r] = v.z;
            As[kq + 3][r] = v.w;
        }
#pragma unroll
        for (int l = 0; l < 4; l++) {
            int i = t + l * 256;
            reinterpret_cast<float4*>(&Bs[0][0])[i] =
                reinterpret_cast<const float4*>(&W[(size_t)k0 * DIM])[i];
        }
        __syncthreads();

#pragma unroll
        for (int k = 0; k < 32; k++) {
            float a[8], b[4];
#pragma unroll
            for (int i = 0; i < 8; i++) a[i] = As[k][tm * 8 + i];
            float4 bv = *reinterpret_cast<const float4*>(&Bs[k][tn * 4]);
            b[0] = bv.x; b[1] = bv.y; b[2] = bv.z; b[3] = bv.w;
#pragma unroll
            for (int i = 0; i < 8; i++)
#pragma unroll
                for (int j = 0; j < 4; j++) acc[i][j] += a[i] * b[j];
        }
        __syncthreads();
    }

#pragma unroll
    for (int i = 0; i < 8; i++) {
        int r = row0 + tm * 8 + i;
        if (r < nrows) {
            int dg = degs[r];
            float inv = rsqrtf((float)(dg > 0 ? dg : 1));
            float4 v = make_float4(acc[i][0] * inv, acc[i][1] * inv,
                                   acc[i][2] * inv, acc[i][3] * inv);
            *reinterpret_cast<float4*>(&H[(size_t)r * DIM + tn * 4]) = v;
        }
    }
}

// ---------------------------------------------------------------------
// Fused edge scatter: one warp per edge (3E edges total).
// h rows are pre-scaled by rsqrt(deg_s); here apply rsqrt(deg_t[dst])
// and a single red.global.add.v4 per lane.
// ---------------------------------------------------------------------
__global__ __launch_bounds__(256) void scatter_kernel(
    const int* __restrict__ src_ab, const int* __restrict__ dst_ab,
    const int* __restrict__ src_ba, const int* __restrict__ dst_ba,
    const int* __restrict__ src_aa, const int* __restrict__ dst_aa,
    float* __restrict__ out_a, float* __restrict__ out_b) {

    long long gw = (long long)blockIdx.x * (blockDim.x >> 5) + (threadIdx.x >> 5);
    int lane = threadIdx.x & 31;
    if (gw >= 3LL * EE) return;

    const float* h;
    float* out;
    const int* sp;
    const int* dp;
    const int* degt;
    long long e;
    if (gw < EE) {
        e = gw;            sp = src_ab; dp = dst_ab; h = g_h_ab; out = out_b;
        degt = g_deg_t_ab;
    } else if (gw < 2LL * EE) {
        e = gw - EE;       sp = src_ba; dp = dst_ba; h = g_h_ba; out = out_a;
        degt = g_deg_t_ba;
    } else {
        e = gw - 2LL * EE; sp = src_aa; dp = dst_aa; h = g_h_aa; out = out_a;
        degt = g_deg_t_aa;
    }

    int s = sp[e];
    int d = dp[e];
    float inv = rsqrtf((float)degt[d]);   // deg_t[dst] >= 1 on every edge

    float4 v = *reinterpret_cast<const float4*>(&h[(size_t)s * DIM + lane * 4]);
    float* o = &out[(size_t)d * DIM + lane * 4];
    red_add_v4(o, v.x * inv, v.y * inv, v.z * inv, v.w * inv);
}

// ---------------------------------------------------------------------
// Finalize: out_a *= 0.5, ReLU everywhere (in place on d_out)
// ---------------------------------------------------------------------
__global__ void finalize_kernel(float* __restrict__ out) {
    const int nA4 = NA * DIM / 4;
    const int nTot4 = (NA + NB) * DIM / 4;
    int i = blockIdx.x * blockDim.x + threadIdx.x;
    if (i >= nTot4) return;
    float4 v = reinterpret_cast<float4*>(out)[i];
    if (i < nA4) {
        v.x *= 0.5f; v.y *= 0.5f; v.z *= 0.5f; v.w *= 0.5f;
    }
    v.x = fmaxf(v.x, 0.f);
    v.y = fmaxf(v.y, 0.f);
    v.z = fmaxf(v.z, 0.f);
    v.w = fmaxf(v.w, 0.f);
    reinterpret_cast<float4*>(out)[i] = v;
}

// ---------------------------------------------------------------------
extern "C" void kernel_launch(void* const* d_in, const int* in_sizes, int n_in,
                              void* d_out, int out_size) {
    const float* x_a  = (const float*)d_in[0];
    const float* x_b  = (const float*)d_in[1];
    const float* W_ab = (const float*)d_in[2];
    const float* W_ba = (const float*)d_in[3];
    const float* W_aa = (const float*)d_in[4];
    const int* src_ab = (const int*)d_in[5];
    const int* dst_ab = (const int*)d_in[6];
    const int* src_ba = (const int*)d_in[7];
    const int* dst_ba = (const int*)d_in[8];
    const int* src_aa = (const int*)d_in[9];
    const int* dst_aa = (const int*)d_in[10];

    float* out   = (float*)d_out;
    float* out_a = out;                       // [NA,128]
    float* out_b = out + (size_t)NA * DIM;    // [NB,128]

    float *h_ab, *h_ba, *h_aa;
    cudaGetSymbolAddress((void**)&h_ab, g_h_ab);
    cudaGetSymbolAddress((void**)&h_ba, g_h_ba);
    cudaGetSymbolAddress((void**)&h_aa, g_h_aa);

    int *d_s_ab, *d_s_ba, *d_s_aa;
    cudaGetSymbolAddress((void**)&d_s_ab, g_deg_s_ab);
    cudaGetSymbolAddress((void**)&d_s_ba, g_deg_s_ba);
    cudaGetSymbolAddress((void**)&d_s_aa, g_deg_s_aa);

    const int nTotF4 = (NA + NB) * DIM / 4;

    zero_kernel<<<1024, 256>>>(out, nTotF4);

    degree_kernel<<<(EE + 255) / 256, 256>>>(src_ab, dst_ab, src_ba, dst_ba, src_aa, dst_aa);

    gemm128_kernel<<<(NA + 63) / 64, 256>>>(x_a, W_ab, h_ab, d_s_ab, NA);
    gemm128_kernel<<<(NB + 63) / 64, 256>>>(x_b, W_ba, h_ba, d_s_ba, NB);
    gemm128_kernel<<<(NA + 63) / 64, 256>>>(x_a, W_aa, h_aa, d_s_aa, NA);

    long long nwarps = 3LL * EE;
    int blocks = (int)((nwarps + 7) / 8);
    scatter_kernel<<<blocks, 256>>>(src_ab, dst_ab, src_ba, dst_ba, src_aa, dst_aa,
                                    out_a, out_b);

    finalize_kernel<<<(nTotF4 + 255) / 256, 256>>>(out);
}

// round 3
// speedup vs baseline: 1.9406x; 1.1582x over previous
#include <cuda_runtime.h>
#include <cuda_bf16.h>

#define NA 100000
#define NB 50000
#define DIM 128
#define EE 1000000

// ---- static device scratch ----
__device__ float g_h_ab[(size_t)NA * DIM];   // (x_a @ W_ab) * rsqrt(deg_s_ab)  -> out_b
__device__ float g_h_ba[(size_t)NB * DIM];   // (x_b @ W_ba) * rsqrt(deg_s_ba)  -> out_a
__device__ float g_h_aa[(size_t)NA * DIM];   // (x_a @ W_aa) * rsqrt(deg_s_aa)  -> out_a

__device__ int g_deg_s_ab[NA];
__device__ int g_deg_t_ab[NB];
__device__ int g_deg_s_ba[NB];
__device__ int g_deg_t_ba[NA];
__device__ int g_deg_s_aa[NA];
__device__ int g_deg_t_aa[NA];

// CSR-by-dst: row starts, fill cursors, and src index buckets
__device__ int g_rs_ab[NB];
__device__ int g_rs_ba[NA];
__device__ int g_rs_aa[NA];
__device__ int g_cur_ab[NB];
__device__ int g_cur_ba[NA];
__device__ int g_cur_aa[NA];
__device__ int g_csr_ab[EE];
__device__ int g_csr_ba[EE];
__device__ int g_csr_aa[EE];

// ---------------------------------------------------------------------
// Zero degree arrays
// ---------------------------------------------------------------------
__global__ void zero_kernel() {
    int i = blockIdx.x * blockDim.x + threadIdx.x;
    int stride = gridDim.x * blockDim.x;
    for (int j = i; j < NA; j += stride) {
        g_deg_s_ab[j] = 0;
        g_deg_t_ba[j] = 0;
        g_deg_s_aa[j] = 0;
        g_deg_t_aa[j] = 0;
    }
    for (int j = i; j < NB; j += stride) {
        g_deg_t_ab[j] = 0;
        g_deg_s_ba[j] = 0;
    }
}

// ---------------------------------------------------------------------
// Degree histograms for all 3 edge types
// ---------------------------------------------------------------------
__global__ void degree_kernel(const int* __restrict__ src_ab, const int* __restrict__ dst_ab,
                              const int* __restrict__ src_ba, const int* __restrict__ dst_ba,
                              const int* __restrict__ src_aa, const int* __restrict__ dst_aa) {
    int i = blockIdx.x * blockDim.x + threadIdx.x;
    if (i >= EE) return;
    atomicAdd(&g_deg_s_ab[src_ab[i]], 1);
    atomicAdd(&g_deg_t_ab[dst_ab[i]], 1);
    atomicAdd(&g_deg_s_ba[src_ba[i]], 1);
    atomicAdd(&g_deg_t_ba[dst_ba[i]], 1);
    atomicAdd(&g_deg_s_aa[src_aa[i]], 1);
    atomicAdd(&g_deg_t_aa[dst_aa[i]], 1);
}

// ---------------------------------------------------------------------
// Exclusive scan of the 3 dst-degree arrays (one block per array).
// 1024 threads, each handles a contiguous chunk, Hillis-Steele on partials.
// ---------------------------------------------------------------------
__global__ __launch_bounds__(1024) void scan3_kernel() {
    const int* deg;
    int n;
    int* rs;
    int* cur;
    if (blockIdx.x == 0)      { deg = g_deg_t_ab; n = NB; rs = g_rs_ab; cur = g_cur_ab; }
    else if (blockIdx.x == 1) { deg = g_deg_t_ba; n = NA; rs = g_rs_ba; cur = g_cur_ba; }
    else                      { deg = g_deg_t_aa; n = NA; rs = g_rs_aa; cur = g_cur_aa; }

    const int t = threadIdx.x;
    const int chunk = (n + 1023) >> 10;
    const int lo = t * chunk;
    const int hi = min(lo + chunk, n);

    int s = 0;
    for (int i = lo; i < hi; i++) s += deg[i];

    __shared__ int sm[1024];
    sm[t] = s;
    __syncthreads();
    for (int off = 1; off < 1024; off <<= 1) {
        int v = (t >= off) ? sm[t - off] : 0;
        __syncthreads();
        sm[t] += v;
        __syncthreads();
    }
    int base = (t > 0) ? sm[t - 1] : 0;
    for (int i = lo; i < hi; i++) {
        rs[i] = base;
        cur[i] = base;
        base += deg[i];
    }
}

// ---------------------------------------------------------------------
// Fill CSR buckets (order within a bucket irrelevant for a sum)
// ---------------------------------------------------------------------
__global__ void fill_kernel(const int* __restrict__ src_ab, const int* __restrict__ dst_ab,
                            const int* __restrict__ src_ba, const int* __restrict__ dst_ba,
                            const int* __restrict__ src_aa, const int* __restrict__ dst_aa) {
    int i = blockIdx.x * blockDim.x + threadIdx.x;
    if (i >= EE) return;
    int p;
    p = atomicAdd(&g_cur_ab[dst_ab[i]], 1); g_csr_ab[p] = src_ab[i];
    p = atomicAdd(&g_cur_ba[dst_ba[i]], 1); g_csr_ba[p] = src_ba[i];
    p = atomicAdd(&g_cur_aa[dst_aa[i]], 1); g_csr_aa[p] = src_aa[i];
}

// ---------------------------------------------------------------------
// SGEMM: H = (X @ W) * rsqrt(deg_s[row])
// BM=64, BN=128, BK=32, 256 threads, 8x4 micro-tile.
// ---------------------------------------------------------------------
__global__ __launch_bounds__(256) void gemm128_kernel(const float* __restrict__ X,
                                                      const float* __restrict__ W,
                                                      float* __restrict__ H,
                                                      const int* __restrict__ degs,
                                                      int nrows) {
    __shared__ float As[32][65];
    __shared__ float Bs[32][128];

    const int t = threadIdx.x;
    const int tn = t & 31;
    const int tm = t >> 5;
    const int row0 = blockIdx.x * 64;

    float acc[8][4];
#pragma unroll
    for (int i = 0; i < 8; i++)
#pragma unroll
        for (int j = 0; j < 4; j++) acc[i][j] = 0.f;

    for (int k0 = 0; k0 < 128; k0 += 32) {
#pragma unroll
        for (int l = 0; l < 2; l++) {
            int i = t + l * 256;
            int r = i >> 3;
            int kq = (i & 7) * 4;
            float4 v = make_float4(0.f, 0.f, 0.f, 0.f);
            if (row0 + r < nrows)
                v = *reinterpret_cast<const float4*>(&X[(size_t)(row0 + r) * DIM + k0 + kq]);
            As[kq + 0][r] = v.x;
            As[kq + 1][r] = v.y;
            As[kq + 2][r] = v.z;
            As[kq + 3][r] = v.w;
        }
#pragma unroll
        for (int l = 0; l < 4; l++) {
            int i = t + l * 256;
            reinterpret_cast<float4*>(&Bs[0][0])[i] =
                reinterpret_cast<const float4*>(&W[(size_t)k0 * DIM])[i];
        }
        __syncthreads();

#pragma unroll
        for (int k = 0; k < 32; k++) {
            float a[8], b[4];
#pragma unroll
            for (int i = 0; i < 8; i++) a[i] = As[k][tm * 8 + i];
            float4 bv = *reinterpret_cast<const float4*>(&Bs[k][tn * 4]);
            b[0] = bv.x; b[1] = bv.y; b[2] = bv.z; b[3] = bv.w;
#pragma unroll
            for (int i = 0; i < 8; i++)
#pragma unroll
                for (int j = 0; j < 4; j++) acc[i][j] += a[i] * b[j];
        }
        __syncthreads();
    }

#pragma unroll
    for (int i = 0; i < 8; i++) {
        int r = row0 + tm * 8 + i;
        if (r < nrows) {
            int dg = degs[r];
            float inv = rsqrtf((float)(dg > 0 ? dg : 1));
            float4 v = make_float4(acc[i][0] * inv, acc[i][1] * inv,
                                   acc[i][2] * inv, acc[i][3] * inv);
            *reinterpret_cast<float4*>(&H[(size_t)r * DIM + tn * 4]) = v;
        }
    }
}

// ---------------------------------------------------------------------
// Warp-per-node gather accumulate: lane owns 4 columns.
// Batch-loads 32 edge ids coalesced, shfl-broadcasts each.
// ---------------------------------------------------------------------
__device__ __forceinline__ float4 gather_accum(const int* __restrict__ csr,
                                               int start, int cnt,
                                               const float* __restrict__ h, int lane) {
    float4 acc = make_float4(0.f, 0.f, 0.f, 0.f);
    int j = 0;
    while (j < cnt) {
        int m = min(32, cnt - j);
        int idx = (lane < m) ? csr[start + j + lane] : 0;
#pragma unroll 4
        for (int k = 0; k < m; k++) {
            int s = __shfl_sync(0xffffffffu, idx, k);
            float4 v = *reinterpret_cast<const float4*>(&h[(size_t)s * DIM + lane * 4]);
            acc.x += v.x; acc.y += v.y; acc.z += v.z; acc.w += v.w;
        }
        j += m;
    }
    return acc;
}

// ---------------------------------------------------------------------
// One warp per output node. a-nodes combine two edge lists (ba, aa),
// b-nodes one (ab). Applies rsqrt(deg_t), 0.5 for a-block, ReLU; plain store.
// Covers ALL rows, so no output zeroing / finalize needed.
// ---------------------------------------------------------------------
__global__ __launch_bounds__(256) void gather_kernel(float* __restrict__ out_a,
                                                     float* __restrict__ out_b) {
    long long gw = (long long)blockIdx.x * (blockDim.x >> 5) + (threadIdx.x >> 5);
    int lane = threadIdx.x & 31;
    if (gw >= (long long)(NA + NB)) return;

    if (gw < NA) {
        int d = (int)gw;
        int c_ba = g_deg_t_ba[d];
        int c_aa = g_deg_t_aa[d];
        float4 s_ba = gather_accum(g_csr_ba, g_rs_ba[d], c_ba, g_h_ba, lane);
        float4 s_aa = gather_accum(g_csr_aa, g_rs_aa[d], c_aa, g_h_aa, lane);
        float rb = (c_ba > 0) ? rsqrtf((float)c_ba) * 0.5f : 0.f;
        float ra = (c_aa > 0) ? rsqrtf((float)c_aa) * 0.5f : 0.f;
        float4 v;
        v.x = fmaxf(s_ba.x * rb + s_aa.x * ra, 0.f);
        v.y = fmaxf(s_ba.y * rb + s_aa.y * ra, 0.f);
        v.z = fmaxf(s_ba.z * rb + s_aa.z * ra, 0.f);
        v.w = fmaxf(s_ba.w * rb + s_aa.w * ra, 0.f);
        *reinterpret_cast<float4*>(&out_a[(size_t)d * DIM + lane * 4]) = v;
    } else {
        int d = (int)(gw - NA);
        int c_ab = g_deg_t_ab[d];
        float4 s_ab = gather_accum(g_csr_ab, g_rs_ab[d], c_ab, g_h_ab, lane);
        float r = (c_ab > 0) ? rsqrtf((float)c_ab) : 0.f;
        float4 v;
        v.x = fmaxf(s_ab.x * r, 0.f);
        v.y = fmaxf(s_ab.y * r, 0.f);
        v.z = fmaxf(s_ab.z * r, 0.f);
        v.w = fmaxf(s_ab.w * r, 0.f);
        *reinterpret_cast<float4*>(&out_b[(size_t)d * DIM + lane * 4]) = v;
    }
}

// ---------------------------------------------------------------------
extern "C" void kernel_launch(void* const* d_in, const int* in_sizes, int n_in,
                              void* d_out, int out_size) {
    const float* x_a  = (const float*)d_in[0];
    const float* x_b  = (const float*)d_in[1];
    const float* W_ab = (const float*)d_in[2];
    const float* W_ba = (const float*)d_in[3];
    const float* W_aa = (const float*)d_in[4];
    const int* src_ab = (const int*)d_in[5];
    const int* dst_ab = (const int*)d_in[6];
    const int* src_ba = (const int*)d_in[7];
    const int* dst_ba = (const int*)d_in[8];
    const int* src_aa = (const int*)d_in[9];
    const int* dst_aa = (const int*)d_in[10];

    float* out   = (float*)d_out;
    float* out_a = out;                       // [NA,128]
    float* out_b = out + (size_t)NA * DIM;    // [NB,128]

    float *h_ab, *h_ba, *h_aa;
    cudaGetSymbolAddress((void**)&h_ab, g_h_ab);
    cudaGetSymbolAddress((void**)&h_ba, g_h_ba);
    cudaGetSymbolAddress((void**)&h_aa, g_h_aa);

    int *d_s_ab, *d_s_ba, *d_s_aa;
    cudaGetSymbolAddress((void**)&d_s_ab, g_deg_s_ab);
    cudaGetSymbolAddress((void**)&d_s_ba, g_deg_s_ba);
    cudaGetSymbolAddress((void**)&d_s_aa, g_deg_s_aa);

    zero_kernel<<<512, 256>>>();

    degree_kernel<<<(EE + 255) / 256, 256>>>(src_ab, dst_ab, src_ba, dst_ba, src_aa, dst_aa);

    scan3_kernel<<<3, 1024>>>();

    fill_kernel<<<(EE + 255) / 256, 256>>>(src_ab, dst_ab, src_ba, dst_ba, src_aa, dst_aa);

    gemm128_kernel<<<(NA + 63) / 64, 256>>>(x_a, W_ab, h_ab, d_s_ab, NA);
    gemm128_kernel<<<(NB + 63) / 64, 256>>>(x_b, W_ba, h_ba, d_s_ba, NB);
    gemm128_kernel<<<(NA + 63) / 64, 256>>>(x_a, W_aa, h_aa, d_s_aa, NA);

    // one warp per output node
    long long nwarps = NA + NB;
    int blocks = (int)((nwarps + 7) / 8);
    gather_kernel<<<blocks, 256>>>(out_a, out_b);
}